// round 9
// baseline (speedup 1.0000x reference)
#include <cuda_runtime.h>
#include <cuda_fp16.h>
#include <mma.h>
#include <math.h>
#include <stdint.h>

using namespace nvcuda;

#define Bdim 2
#define Lq 8192
#define Edim 1024
#define Hn 16
#define Dh 64
#define Cch 256
#define Nch (Lq / Cch)            // 32
#define BL (Bdim * Lq)            // 16384
#define NCHUNKS (Bdim * Hn * Nch) // 1024

// ---------------- scratch (device globals: no allocation allowed) ----------
__device__ float g_q[BL * Edim];
__device__ float g_k[BL * Edim];
__device__ float g_v[BL * Edim];
__device__ float g_attn[BL * Edim];
__device__ float g_y[BL * Edim];
__device__ float g_Sc[NCHUNKS * Dh * Dh];
__device__ float g_Sp[NCHUNKS * Dh * Dh];
__device__ float g_zc[NCHUNKS * Dh];
__device__ float g_zp[NCHUNKS * Dh];

// ============================ helpers =======================================
// convert 8 fp32 (two float4) -> 8 fp16 hi + 8 fp16 lo, stored as 16B each
__device__ __forceinline__ void g2_cvt8(float4 v0, float4 v1,
                                        __half* __restrict__ hd,
                                        __half* __restrict__ ld)
{
    float a[8] = {v0.x, v0.y, v0.z, v0.w, v1.x, v1.y, v1.z, v1.w};
    __half2 h[4], l[4];
#pragma unroll
    for (int i = 0; i < 4; i++) {
        float x = a[2 * i], y = a[2 * i + 1];
        __half hx = __float2half_rn(x), hy = __float2half_rn(y);
        h[i] = __halves2half2(hx, hy);
        l[i] = __halves2half2(
            __float2half_rn(__fsub_rn(x, __half2float(hx))),
            __float2half_rn(__fsub_rn(y, __half2float(hy))));
    }
    *(float4*)hd = *(float4*)h;
    *(float4*)ld = *(float4*)l;
}

// ============================ FP16x3 WMMA GEMM v2 ===========================
// D[m][k]*W[k][n]; compensated AhWh + AhWl + AlWh. LDG->regs->cvt->half smem.
// ACT: 0 none, 1 phi(elu+1), 2 +resid ; OSEL: 0 g_q, 1 g_k, 2 g_v, 3 g_y
// ISEL: 0 = Ain param, 1 = g_attn
#define BK2 16
#define NK2 (Edim / BK2)               // 64
#define LDAH 24                        // halfs per A half-row
#define LDBH 136                       // halfs per B half-row
#define AH_OFF 0
#define AL_OFF (128 * LDAH)            // 3072
#define BH_OFF (2 * 128 * LDAH)        // 6144
#define BL_OFF (BH_OFF + 16 * LDBH)    // 8320
#define STAGE_H (2 * 128 * LDAH + 2 * 16 * LDBH)  // 10496 halfs (20992 B)
#define GSMB 65536                     // epilogue staging needs 64KB

template <int ACT, int OSEL, int ISEL>
__global__ void __launch_bounds__(256, 2) g2_gemm_kernel(
    const float* __restrict__ Ain, const float* __restrict__ W,
    const float* __restrict__ bias, const float* __restrict__ resid)
{
    extern __shared__ __half smh[];
    int tid = threadIdx.x;
    int lane = tid & 31, wid = tid >> 5;

    const float* A = (ISEL == 0) ? Ain : &g_attn[0];
    float* Cout = (OSEL == 0) ? &g_q[0] : (OSEL == 1) ? &g_k[0]
                : (OSEL == 2) ? &g_v[0] : &g_y[0];

    int bm = blockIdx.y * 128;
    int bn = blockIdx.x * 128;

    // ---- load mapping: A tile 128x16 f32, B tile 16x128 f32 ----
    int arow = tid >> 1, acol = (tid & 1) * 8;
    int brow = tid >> 4, bcol = (tid & 15) * 8;
    const float* gA = A + (size_t)(bm + arow) * Edim + acol;
    const float* gW = W + (size_t)brow * Edim + bn + bcol;
    uint32_t a_sofs = (uint32_t)(arow * LDAH + acol);
    uint32_t b_sofs = (uint32_t)(brow * LDBH + bcol);

    float4 ra0, ra1, rb0, rb1;
    ra0 = *(const float4*)(gA);
    ra1 = *(const float4*)(gA + 4);
    rb0 = *(const float4*)(gW);
    rb1 = *(const float4*)(gW + 4);

#define STORE_STAGE(stg) do {                                            \
    __half* s_ = smh + (uint32_t)(stg) * STAGE_H;                        \
    g2_cvt8(ra0, ra1, s_ + AH_OFF + a_sofs, s_ + AL_OFF + a_sofs);       \
    g2_cvt8(rb0, rb1, s_ + BH_OFF + b_sofs, s_ + BL_OFF + b_sofs);       \
} while (0)

    STORE_STAGE(0);
    __syncthreads();

    int Mb = (wid & 1) * 64;
    int Nb = (wid >> 1) * 32;

    wmma::fragment<wmma::accumulator, 16, 16, 16, float> acc[4][2];
#pragma unroll
    for (int mt = 0; mt < 4; mt++)
#pragma unroll
        for (int nt = 0; nt < 2; nt++) wmma::fill_fragment(acc[mt][nt], 0.0f);

    for (int kt = 0; kt < NK2; kt++) {
        if (kt + 1 < NK2) {
            const float* aP = gA + (size_t)(kt + 1) * BK2;
            const float* bP = gW + (size_t)(kt + 1) * BK2 * Edim;
            ra0 = *(const float4*)(aP);
            ra1 = *(const float4*)(aP + 4);
            rb0 = *(const float4*)(bP);
            rb1 = *(const float4*)(bP + 4);
        }

        const __half* st = smh + (uint32_t)(kt & 1) * STAGE_H;
#pragma unroll
        for (int nt = 0; nt < 2; nt++) {
            wmma::fragment<wmma::matrix_b, 16, 16, 16, __half, wmma::row_major> fbh, fbl;
            wmma::load_matrix_sync(fbh, st + BH_OFF + Nb + nt * 16, LDBH);
            wmma::load_matrix_sync(fbl, st + BL_OFF + Nb + nt * 16, LDBH);
#pragma unroll
            for (int mt = 0; mt < 4; mt++) {
                wmma::fragment<wmma::matrix_a, 16, 16, 16, __half, wmma::row_major> fah, fal;
                wmma::load_matrix_sync(fah, st + AH_OFF + (Mb + mt * 16) * LDAH, LDAH);
                wmma::load_matrix_sync(fal, st + AL_OFF + (Mb + mt * 16) * LDAH, LDAH);
                wmma::mma_sync(acc[mt][nt], fah, fbl, acc[mt][nt]);
                wmma::mma_sync(acc[mt][nt], fal, fbh, acc[mt][nt]);
                wmma::mma_sync(acc[mt][nt], fah, fbh, acc[mt][nt]);
            }
        }

        if (kt + 1 < NK2) {
            __syncthreads();            // all warps done reading other stage
            STORE_STAGE((kt + 1) & 1);
            __syncthreads();            // stores visible
        }
    }

    __syncthreads();   // tile region reused by epilogue staging

    // ---- epilogue: per-warp 64x32 f32 smem staging ----
    float* wst = (float*)smh + wid * (64 * 32);
#pragma unroll
    for (int mt = 0; mt < 4; mt++)
#pragma unroll
        for (int nt = 0; nt < 2; nt++)
            wmma::store_matrix_sync(wst + mt * 16 * 32 + nt * 16, acc[mt][nt],
                                    32, wmma::mem_row_major);
    __syncwarp();

    for (int e = lane; e < 64 * 8; e += 32) {
        int r = e >> 3, cb = (e & 7) * 4;
        float4 v = *(float4*)(wst + r * 32 + cb);
        int grow = bm + Mb + r;
        int gcol = bn + Nb + cb;
        float4 bb = *(const float4*)&bias[gcol];
        v.x += bb.x; v.y += bb.y; v.z += bb.z; v.w += bb.w;
        if (ACT == 1) {
            v.x = v.x > 0.f ? v.x + 1.f : expf(v.x);
            v.y = v.y > 0.f ? v.y + 1.f : expf(v.y);
            v.z = v.z > 0.f ? v.z + 1.f : expf(v.z);
            v.w = v.w > 0.f ? v.w + 1.f : expf(v.w);
        }
        if (ACT == 2) {
            float4 xr = *(const float4*)&resid[(size_t)grow * Edim + gcol];
            v.x += xr.x; v.y += xr.y; v.z += xr.z; v.w += xr.w;
        }
        *(float4*)&Cout[(size_t)grow * Edim + gcol] = v;
    }
#undef STORE_STAGE
}

// ---------------- per-chunk KV stats (512 threads) ---------------------------
__global__ void __launch_bounds__(512) g2_chunk_stats_kernel()
{
    __shared__ float ks[64][64];
    __shared__ float vs[64][64];
    int blk = blockIdx.x;
    int n = blk % Nch;
    int h = (blk / Nch) % Hn;
    int b = blk / (Nch * Hn);
    int rowbase = b * Lq + n * Cch;
    int colbase = h * Dh;
    int t = threadIdx.x;
    int d = t >> 3;                 // 0..63
    int e0 = (t & 7) * 8;           // 0..56

    float acc[8];
#pragma unroll
    for (int j = 0; j < 8; j++) acc[j] = 0.f;
    float zacc = 0.f;

    for (int st = 0; st < Cch; st += 64) {
        for (int i = t; i < 1024; i += 512) {
            int r = i >> 4, c4 = (i & 15) * 4;
            size_t gofs = (size_t)(rowbase + st + r) * Edim + colbase + c4;
            *(float4*)&ks[r][c4] = *(const float4*)&g_k[gofs];
            *(float4*)&vs[r][c4] = *(const float4*)&g_v[gofs];
        }
        __syncthreads();
#pragma unroll 4
        for (int s = 0; s < 64; s++) {
            float kd = ks[s][d];
            float4 v0 = *(const float4*)&vs[s][e0];
            float4 v1 = *(const float4*)&vs[s][e0 + 4];
            acc[0] += kd * v0.x; acc[1] += kd * v0.y;
            acc[2] += kd * v0.z; acc[3] += kd * v0.w;
            acc[4] += kd * v1.x; acc[5] += kd * v1.y;
            acc[6] += kd * v1.z; acc[7] += kd * v1.w;
            zacc += kd;
        }
        __syncthreads();
    }

    float* Sb = &g_Sc[(size_t)blk * (Dh * Dh) + d * 64 + e0];
    float4 o0, o1;
    o0.x = acc[0]; o0.y = acc[1]; o0.z = acc[2]; o0.w = acc[3];
    o1.x = acc[4]; o1.y = acc[5]; o1.z = acc[6]; o1.w = acc[7];
    *(float4*)(Sb + 0) = o0;
    *(float4*)(Sb + 4) = o1;
    if ((t & 7) == 0) g_zc[blk * Dh + d] = zacc;
}

// ---------------- exclusive prefix scan over chunks per (b,h) ---------------
__global__ void __launch_bounds__(256) g2_scan_kernel()
{
    int bh = blockIdx.x;
    int t = threadIdx.x;
    float run[16];
#pragma unroll
    for (int i = 0; i < 16; i++) run[i] = 0.f;
    float zrun = 0.f;

    for (int n = 0; n < Nch; n++) {
        size_t base = ((size_t)bh * Nch + n) * (Dh * Dh);
#pragma unroll
        for (int i = 0; i < 16; i++) {
            int idx = t + i * 256;
            g_Sp[base + idx] = run[i];
            run[i] += g_Sc[base + idx];
        }
        if (t < Dh) {
            size_t zb = ((size_t)bh * Nch + n) * Dh + t;
            g_zp[zb] = zrun;
            zrun += g_zc[zb];
        }
    }
}

// ---------------- per-chunk attention output (512 threads, 2/row) ------------
__global__ void __launch_bounds__(512, 1) g2_chunk_out_kernel()
{
    __shared__ float ks[64][64];
    __shared__ float vs[64][64];
    int blk = blockIdx.x;
    int n = blk % Nch;
    int h = (blk / Nch) % Hn;
    int b = blk / (Nch * Hn);
    int rowbase = b * Lq + n * Cch;
    int colbase = h * Dh;
    int t = threadIdx.x;
    int row = t >> 1;               // 0..255
    int hf = t & 1;                 // output half: dims [hf*32, hf*32+32)

    const float* qrow = &g_q[(size_t)(rowbase + row) * Edim + colbase];

    float qv[64];
#pragma unroll
    for (int j = 0; j < 16; j++) {
        float4 qq = *(const float4*)(qrow + 4 * j);
        qv[4 * j + 0] = qq.x; qv[4 * j + 1] = qq.y;
        qv[4 * j + 2] = qq.z; qv[4 * j + 3] = qq.w;
    }

    float acc[32];
#pragma unroll
    for (int j = 0; j < 32; j++) acc[j] = 0.f;

    // q @ S_prefix over my 32 output dims
    const float* Sb = &g_Sp[(size_t)blk * (Dh * Dh) + hf * 32];
    for (int d = 0; d < 64; d++) {
        float qd = qv[d];
        const float4* S4 = (const float4*)(Sb + d * 64);
#pragma unroll
        for (int j = 0; j < 8; j++) {
            float4 sv = __ldg(S4 + j);
            acc[4 * j + 0] += qd * sv.x;
            acc[4 * j + 1] += qd * sv.y;
            acc[4 * j + 2] += qd * sv.z;
            acc[4 * j + 3] += qd * sv.w;
        }
    }

    // den = q . z_prefix (computed redundantly by both half-threads)
    float den = 0.f;
    const float* zb = &g_zp[(size_t)blk * Dh];
#pragma unroll
    for (int j = 0; j < 16; j++) {
        den += qv[4 * j + 0] * __ldg(zb + 4 * j + 0);
        den += qv[4 * j + 1] * __ldg(zb + 4 * j + 1);
        den += qv[4 * j + 2] * __ldg(zb + 4 * j + 2);
        den += qv[4 * j + 3] * __ldg(zb + 4 * j + 3);
    }

    // intra-chunk causal part, tiled over s in blocks of 64
    for (int st = 0; st < Cch; st += 64) {
        for (int i = t; i < 1024; i += 512) {
            int r = i >> 4, c4 = (i & 15) * 4;
            size_t gofs = (size_t)(rowbase + st + r) * Edim + colbase + c4;
            *(float4*)&ks[r][c4] = *(const float4*)&g_k[gofs];
            *(float4*)&vs[r][c4] = *(const float4*)&g_v[gofs];
        }
        __syncthreads();
        int smax = row - st + 1;
        if (smax > 64) smax = 64;
        for (int s = 0; s < smax; s++) {
            const float4* k4 = (const float4*)&ks[s][0];
            float dot = 0.f;
#pragma unroll
            for (int j = 0; j < 16; j++) {
                float4 kk = k4[j];
                dot += qv[4 * j + 0] * kk.x + qv[4 * j + 1] * kk.y
                     + qv[4 * j + 2] * kk.z + qv[4 * j + 3] * kk.w;
            }
            den += dot;
            const float4* v4 = (const float4*)&vs[s][hf * 32];
#pragma unroll
            for (int j = 0; j < 8; j++) {
                float4 vv = v4[j];
                acc[4 * j + 0] += dot * vv.x;
                acc[4 * j + 1] += dot * vv.y;
                acc[4 * j + 2] += dot * vv.z;
                acc[4 * j + 3] += dot * vv.w;
            }
        }
        __syncthreads();
    }

    float inv = 1.0f / (den + 1e-6f);
    float* orow = &g_attn[(size_t)(rowbase + row) * Edim + colbase + hf * 32];
#pragma unroll
    for (int j = 0; j < 8; j++) {
        float4 o;
        o.x = acc[4 * j + 0] * inv;
        o.y = acc[4 * j + 1] * inv;
        o.z = acc[4 * j + 2] * inv;
        o.w = acc[4 * j + 3] * inv;
        *(float4*)(orow + 4 * j) = o;
    }
}

// ---------------- LayerNorm --------------------------------------------------
__global__ void __launch_bounds__(256) g2_ln_kernel(
    const float* __restrict__ gamma, const float* __restrict__ beta,
    float* __restrict__ out)
{
    int row = blockIdx.x;
    int t = threadIdx.x;
    const float* yr = &g_y[(size_t)row * Edim];
    float4 v = *(const float4*)(yr + t * 4);
    float s = v.x + v.y + v.z + v.w;
    float ss = v.x * v.x + v.y * v.y + v.z * v.z + v.w * v.w;
#pragma unroll
    for (int o = 16; o; o >>= 1) {
        s += __shfl_down_sync(0xffffffffu, s, o);
        ss += __shfl_down_sync(0xffffffffu, ss, o);
    }
    __shared__ float sh_s[8], sh_ss[8];
    int w = t >> 5, ln = t & 31;
    if (ln == 0) { sh_s[w] = s; sh_ss[w] = ss; }
    __syncthreads();
    if (t == 0) {
        float a = 0.f, b2 = 0.f;
#pragma unroll
        for (int i = 0; i < 8; i++) { a += sh_s[i]; b2 += sh_ss[i]; }
        sh_s[0] = a; sh_ss[0] = b2;
    }
    __syncthreads();
    float mu = sh_s[0] * (1.0f / Edim);
    float var = sh_ss[0] * (1.0f / Edim) - mu * mu;
    float rstd = rsqrtf(var + 1e-5f);
    float4 g = *(const float4*)(gamma + t * 4);
    float4 bb = *(const float4*)(beta + t * 4);
    float4 o;
    o.x = g.x * (v.x - mu) * rstd + bb.x;
    o.y = g.y * (v.y - mu) * rstd + bb.y;
    o.z = g.z * (v.z - mu) * rstd + bb.z;
    o.w = g.w * (v.w - mu) * rstd + bb.w;
    *(float4*)(out + (size_t)row * Edim + t * 4) = o;
}

// ---------------- launch ------------------------------------------------------
extern "C" void kernel_launch(void* const* d_in, const int* in_sizes, int n_in,
                              void* d_out, int out_size)
{
    const float* x     = (const float*)d_in[0];
    const float* Wq    = (const float*)d_in[1];
    const float* bq    = (const float*)d_in[2];
    const float* Wk    = (const float*)d_in[3];
    const float* bk    = (const float*)d_in[4];
    const float* Wv    = (const float*)d_in[5];
    const float* bv    = (const float*)d_in[6];
    const float* Wo    = (const float*)d_in[7];
    const float* bo    = (const float*)d_in[8];
    const float* gamma = (const float*)d_in[9];
    const float* beta  = (const float*)d_in[10];
    float* out = (float*)d_out;

    cudaFuncSetAttribute(g2_gemm_kernel<1, 0, 0>, cudaFuncAttributeMaxDynamicSharedMemorySize, GSMB);
    cudaFuncSetAttribute(g2_gemm_kernel<1, 1, 0>, cudaFuncAttributeMaxDynamicSharedMemorySize, GSMB);
    cudaFuncSetAttribute(g2_gemm_kernel<0, 2, 0>, cudaFuncAttributeMaxDynamicSharedMemorySize, GSMB);
    cudaFuncSetAttribute(g2_gemm_kernel<2, 3, 1>, cudaFuncAttributeMaxDynamicSharedMemorySize, GSMB);

    dim3 ggrid(Edim / 128, BL / 128);

    g2_gemm_kernel<1, 0, 0><<<ggrid, 256, GSMB>>>(x, Wq, bq, nullptr);   // q = phi(x@Wq+bq)
    g2_gemm_kernel<1, 1, 0><<<ggrid, 256, GSMB>>>(x, Wk, bk, nullptr);   // k = phi(x@Wk+bk)
    g2_gemm_kernel<0, 2, 0><<<ggrid, 256, GSMB>>>(x, Wv, bv, nullptr);   // v = x@Wv+bv

    g2_chunk_stats_kernel<<<NCHUNKS, 512>>>();
    g2_scan_kernel<<<Bdim * Hn, 256>>>();
    g2_chunk_out_kernel<<<NCHUNKS, 512>>>();

    g2_gemm_kernel<2, 3, 1><<<ggrid, 256, GSMB>>>(nullptr, Wo, bo, x);   // y = attn@Wo+bo+x

    g2_ln_kernel<<<BL, 256>>>(gamma, beta, out);
}

// round 10
// speedup vs baseline: 1.2362x; 1.2362x over previous
#include <cuda_runtime.h>
#include <cuda_fp16.h>
#include <mma.h>
#include <math.h>
#include <stdint.h>

using namespace nvcuda;

#define Bdim 2
#define Lq 8192
#define Edim 1024
#define Hn 16
#define Dh 64
#define Cch 256
#define Nch (Lq / Cch)            // 32
#define BL (Bdim * Lq)            // 16384
#define NCHUNKS (Bdim * Hn * Nch) // 1024

// ---------------- scratch (device globals: no allocation allowed) ----------
__device__ float g_q[BL * Edim];
__device__ float g_k[BL * Edim];
__device__ float g_v[BL * Edim];
__device__ float g_attn[BL * Edim];
__device__ float g_y[BL * Edim];
__device__ float g_Sc[NCHUNKS * Dh * Dh];
__device__ float g_Sp[NCHUNKS * Dh * Dh];
__device__ float g_zc[NCHUNKS * Dh];
__device__ float g_zp[NCHUNKS * Dh];

// ============================ helpers =======================================
__device__ __forceinline__ uint32_t v3_smem_u32(const void* p) {
    uint32_t a;
    asm("{ .reg .u64 t; cvta.to.shared.u64 t, %1; cvt.u32.u64 %0, t; }"
        : "=r"(a) : "l"(p));
    return a;
}

#define CP_ASYNC_16(dst, src) \
    asm volatile("cp.async.cg.shared.global [%0], [%1], 16;" \
        :: "r"(dst), "l"(src))
#define CP_ASYNC_COMMIT() asm volatile("cp.async.commit_group;" ::: "memory")
#define CP_ASYNC_WAIT_1() asm volatile("cp.async.wait_group 1;" ::: "memory")
#define CP_ASYNC_WAIT_0() asm volatile("cp.async.wait_group 0;" ::: "memory")

// split 8 consecutive fp32 -> 8 fp16 hi + 8 fp16 lo (16B stores)
__device__ __forceinline__ void v3_cvt8(const float* __restrict__ s,
                                        __half* __restrict__ hd,
                                        __half* __restrict__ ld)
{
    float4 v0 = *(const float4*)s;
    float4 v1 = *(const float4*)(s + 4);
    float a[8] = {v0.x, v0.y, v0.z, v0.w, v1.x, v1.y, v1.z, v1.w};
    __half2 h[4], l[4];
#pragma unroll
    for (int i = 0; i < 4; i++) {
        float x = a[2 * i], y = a[2 * i + 1];
        __half hx = __float2half_rn(x), hy = __float2half_rn(y);
        h[i] = __halves2half2(hx, hy);
        l[i] = __halves2half2(
            __float2half_rn(__fsub_rn(x, __half2float(hx))),
            __float2half_rn(__fsub_rn(y, __half2float(hy))));
    }
    *(float4*)hd = *(float4*)h;
    *(float4*)ld = *(float4*)l;
}

// ============================ FP16x3 WMMA GEMM (R8 proven) ==================
#define BKh 16
#define NKTh (Edim / BKh)      // 64 k-blocks
#define A_F 2048               // A stage floats (128 x 16)
#define B_F 2048               // B stage floats (16 x 128)
#define STAGEF (A_F + B_F)     // 4096 floats = 16KB per stage
#define LDAH 24                // halfs per Ah/Al row
#define LDBH 136               // halfs per Bh/Bl row
#define GSMB 65536

template <int ACT, int OSEL, int ISEL>
__global__ void __launch_bounds__(256, 2) v3_gemm_kernel(
    const float* __restrict__ Ain, const float* __restrict__ W,
    const float* __restrict__ bias, const float* __restrict__ resid)
{
    extern __shared__ float smf[];
    uint32_t sbase = v3_smem_u32(smf);
    int tid = threadIdx.x;
    int lane = tid & 31, wid = tid >> 5;

    const float* A = (ISEL == 0) ? Ain : &g_attn[0];
    float* Cout = (OSEL == 0) ? &g_q[0] : (OSEL == 1) ? &g_k[0]
                : (OSEL == 2) ? &g_v[0] : &g_y[0];

    int bm = blockIdx.y * 128;
    int bn = blockIdx.x * 128;

    __half* Ah = (__half*)(smf + 2 * STAGEF);
    __half* Al = Ah + 128 * LDAH;
    __half* Bh = Al + 128 * LDAH;
    __half* Bl = Bh + 16 * LDBH;

    int arow = tid >> 1, acol = (tid & 1) * 8;
    int brow = tid >> 4, bcol = (tid & 15) * 8;
    const float* gA = A + (size_t)(bm + arow) * Edim + acol;
    const float* gW = W + (size_t)brow * Edim + bn + bcol;
    uint32_t adst = (uint32_t)(arow * 16 + acol) * 4;
    uint32_t bdst = (uint32_t)(A_F + brow * 128 + bcol) * 4;

#define ISSUE_LOADS(kt, stg) do {                                          \
    uint32_t s0 = sbase + (uint32_t)(stg) * (STAGEF * 4);                  \
    const float* aP = gA + (size_t)(kt) * BKh;                             \
    const float* bP = gW + (size_t)(kt) * BKh * Edim;                      \
    CP_ASYNC_16(s0 + adst,      aP);                                       \
    CP_ASYNC_16(s0 + adst + 16, aP + 4);                                   \
    CP_ASYNC_16(s0 + bdst,      bP);                                       \
    CP_ASYNC_16(s0 + bdst + 16, bP + 4);                                   \
    CP_ASYNC_COMMIT();                                                      \
} while (0)

    int Mb = (wid & 1) * 64;
    int Nb = (wid >> 1) * 32;

    wmma::fragment<wmma::accumulator, 16, 16, 16, float> acc[4][2];
#pragma unroll
    for (int mt = 0; mt < 4; mt++)
#pragma unroll
        for (int nt = 0; nt < 2; nt++) wmma::fill_fragment(acc[mt][nt], 0.0f);

    ISSUE_LOADS(0, 0);

    for (int kt = 0; kt < NKTh; kt++) {
        if (kt + 1 < NKTh) {
            ISSUE_LOADS(kt + 1, (kt + 1) & 1);
            CP_ASYNC_WAIT_1();
        } else {
            CP_ASYNC_WAIT_0();
        }
        __syncthreads();

        const float* sa = smf + (kt & 1) * STAGEF;
        const float* sbm = sa + A_F;
        {
            int ai = tid * 8;
            int ar = ai >> 4, ac = ai & 15;
            v3_cvt8(sa + ai, Ah + ar * LDAH + ac, Al + ar * LDAH + ac);
            int br = tid >> 4, bc = (tid & 15) * 8;
            v3_cvt8(sbm + tid * 8, Bh + br * LDBH + bc, Bl + br * LDBH + bc);
        }
        __syncthreads();

#pragma unroll
        for (int nt = 0; nt < 2; nt++) {
            wmma::fragment<wmma::matrix_b, 16, 16, 16, __half, wmma::row_major> fbh, fbl;
            wmma::load_matrix_sync(fbh, Bh + Nb + nt * 16, LDBH);
            wmma::load_matrix_sync(fbl, Bl + Nb + nt * 16, LDBH);
#pragma unroll
            for (int mt = 0; mt < 4; mt++) {
                wmma::fragment<wmma::matrix_a, 16, 16, 16, __half, wmma::row_major> fah, fal;
                wmma::load_matrix_sync(fah, Ah + (Mb + mt * 16) * LDAH, LDAH);
                wmma::load_matrix_sync(fal, Al + (Mb + mt * 16) * LDAH, LDAH);
                wmma::mma_sync(acc[mt][nt], fah, fbl, acc[mt][nt]);
                wmma::mma_sync(acc[mt][nt], fal, fbh, acc[mt][nt]);
                wmma::mma_sync(acc[mt][nt], fah, fbh, acc[mt][nt]);
            }
        }
    }

    __syncthreads();

    float* wst = smf + wid * (64 * 32);
#pragma unroll
    for (int mt = 0; mt < 4; mt++)
#pragma unroll
        for (int nt = 0; nt < 2; nt++)
            wmma::store_matrix_sync(wst + mt * 16 * 32 + nt * 16, acc[mt][nt],
                                    32, wmma::mem_row_major);
    __syncwarp();

    for (int e = lane; e < 64 * 8; e += 32) {
        int r = e >> 3, cb = (e & 7) * 4;
        float4 v = *(float4*)(wst + r * 32 + cb);
        int grow = bm + Mb + r;
        int gcol = bn + Nb + cb;
        float4 bb = *(const float4*)&bias[gcol];
        v.x += bb.x; v.y += bb.y; v.z += bb.z; v.w += bb.w;
        if (ACT == 1) {
            v.x = v.x > 0.f ? v.x + 1.f : expf(v.x);
            v.y = v.y > 0.f ? v.y + 1.f : expf(v.y);
            v.z = v.z > 0.f ? v.z + 1.f : expf(v.z);
            v.w = v.w > 0.f ? v.w + 1.f : expf(v.w);
        }
        if (ACT == 2) {
            float4 xr = *(const float4*)&resid[(size_t)grow * Edim + gcol];
            v.x += xr.x; v.y += xr.y; v.z += xr.z; v.w += xr.w;
        }
        *(float4*)&Cout[(size_t)grow * Edim + gcol] = v;
    }
#undef ISSUE_LOADS
}

// ---------------- per-chunk KV stats (512 threads, R9 proven) ----------------
__global__ void __launch_bounds__(512) v3_chunk_stats_kernel()
{
    __shared__ float ks[64][64];
    __shared__ float vs[64][64];
    int blk = blockIdx.x;
    int n = blk % Nch;
    int h = (blk / Nch) % Hn;
    int b = blk / (Nch * Hn);
    int rowbase = b * Lq + n * Cch;
    int colbase = h * Dh;
    int t = threadIdx.x;
    int d = t >> 3;
    int e0 = (t & 7) * 8;

    float acc[8];
#pragma unroll
    for (int j = 0; j < 8; j++) acc[j] = 0.f;
    float zacc = 0.f;

    for (int st = 0; st < Cch; st += 64) {
        for (int i = t; i < 1024; i += 512) {
            int r = i >> 4, c4 = (i & 15) * 4;
            size_t gofs = (size_t)(rowbase + st + r) * Edim + colbase + c4;
            *(float4*)&ks[r][c4] = *(const float4*)&g_k[gofs];
            *(float4*)&vs[r][c4] = *(const float4*)&g_v[gofs];
        }
        __syncthreads();
#pragma unroll 4
        for (int s = 0; s < 64; s++) {
            float kd = ks[s][d];
            float4 v0 = *(const float4*)&vs[s][e0];
            float4 v1 = *(const float4*)&vs[s][e0 + 4];
            acc[0] += kd * v0.x; acc[1] += kd * v0.y;
            acc[2] += kd * v0.z; acc[3] += kd * v0.w;
            acc[4] += kd * v1.x; acc[5] += kd * v1.y;
            acc[6] += kd * v1.z; acc[7] += kd * v1.w;
            zacc += kd;
        }
        __syncthreads();
    }

    float* Sb = &g_Sc[(size_t)blk * (Dh * Dh) + d * 64 + e0];
    float4 o0, o1;
    o0.x = acc[0]; o0.y = acc[1]; o0.z = acc[2]; o0.w = acc[3];
    o1.x = acc[4]; o1.y = acc[5]; o1.z = acc[6]; o1.w = acc[7];
    *(float4*)(Sb + 0) = o0;
    *(float4*)(Sb + 4) = o1;
    if ((t & 7) == 0) g_zc[blk * Dh + d] = zacc;
}

// ---------------- exclusive prefix scan over chunks per (b,h) ---------------
__global__ void __launch_bounds__(256) v3_scan_kernel()
{
    int bh = blockIdx.x;
    int t = threadIdx.x;
    float run[16];
#pragma unroll
    for (int i = 0; i < 16; i++) run[i] = 0.f;
    float zrun = 0.f;

    for (int n = 0; n < Nch; n++) {
        size_t base = ((size_t)bh * Nch + n) * (Dh * Dh);
#pragma unroll
        for (int i = 0; i < 16; i++) {
            int idx = t + i * 256;
            g_Sp[base + idx] = run[i];
            run[i] += g_Sc[base + idx];
        }
        if (t < Dh) {
            size_t zb = ((size_t)bh * Nch + n) * Dh + t;
            g_zp[zb] = zrun;
            zrun += g_zc[zb];
        }
    }
}

// ---------------- per-chunk attention output v3 ------------------------------
// 2048 blocks x 128 threads: block = (chunk, row-half). One row per thread,
// full acc[64] (identical arithmetic order to the proven R8 version).
__global__ void __launch_bounds__(128) v3_chunk_out_kernel()
{
    __shared__ float ks[64][64];
    __shared__ float vs[64][64];
    int bid = blockIdx.x;
    int blk = bid >> 1;
    int rh = bid & 1;               // row half: rows [rh*128, rh*128+128)
    int n = blk % Nch;
    int h = (blk / Nch) % Hn;
    int b = blk / (Nch * Hn);
    int rowbase = b * Lq + n * Cch;
    int colbase = h * Dh;
    int t = threadIdx.x;            // 0..127
    int row = rh * 128 + t;         // row within chunk

    const float* qrow = &g_q[(size_t)(rowbase + row) * Edim + colbase];

    float qv[64];
#pragma unroll
    for (int j = 0; j < 16; j++) {
        float4 qq = *(const float4*)(qrow + 4 * j);
        qv[4 * j + 0] = qq.x; qv[4 * j + 1] = qq.y;
        qv[4 * j + 2] = qq.z; qv[4 * j + 3] = qq.w;
    }

    float acc[64];
#pragma unroll
    for (int j = 0; j < 64; j++) acc[j] = 0.f;

    // q @ S_prefix (q re-read via __ldg: keeps dynamic index off registers)
    const float* Sb = &g_Sp[(size_t)blk * (Dh * Dh)];
    for (int d = 0; d < 64; d++) {
        float qd = __ldg(qrow + d);
        const float4* S4 = (const float4*)(Sb + d * 64);
#pragma unroll
        for (int j = 0; j < 16; j++) {
            float4 sv = __ldg(S4 + j);
            acc[4 * j + 0] += qd * sv.x;
            acc[4 * j + 1] += qd * sv.y;
            acc[4 * j + 2] += qd * sv.z;
            acc[4 * j + 3] += qd * sv.w;
        }
    }

    float den = 0.f;
    const float* zb = &g_zp[(size_t)blk * Dh];
#pragma unroll
    for (int j = 0; j < 16; j++) {
        den += qv[4 * j + 0] * __ldg(zb + 4 * j + 0);
        den += qv[4 * j + 1] * __ldg(zb + 4 * j + 1);
        den += qv[4 * j + 2] * __ldg(zb + 4 * j + 2);
        den += qv[4 * j + 3] * __ldg(zb + 4 * j + 3);
    }

    // intra-chunk causal part: lower half needs tiles {0,64}; upper all 4
    int st_limit = (rh + 1) * 128;
    for (int st = 0; st < st_limit; st += 64) {
        for (int i = t; i < 1024; i += 128) {
            int r = i >> 4, c4 = (i & 15) * 4;
            size_t gofs = (size_t)(rowbase + st + r) * Edim + colbase + c4;
            *(float4*)&ks[r][c4] = *(const float4*)&g_k[gofs];
            *(float4*)&vs[r][c4] = *(const float4*)&g_v[gofs];
        }
        __syncthreads();
        int smax = row - st + 1;
        if (smax > 64) smax = 64;
        for (int s = 0; s < smax; s++) {
            const float4* k4 = (const float4*)&ks[s][0];
            float dot = 0.f;
#pragma unroll
            for (int j = 0; j < 16; j++) {
                float4 kk = k4[j];
                dot += qv[4 * j + 0] * kk.x + qv[4 * j + 1] * kk.y
                     + qv[4 * j + 2] * kk.z + qv[4 * j + 3] * kk.w;
            }
            den += dot;
            const float4* v4 = (const float4*)&vs[s][0];
#pragma unroll
            for (int j = 0; j < 16; j++) {
                float4 vv = v4[j];
                acc[4 * j + 0] += dot * vv.x;
                acc[4 * j + 1] += dot * vv.y;
                acc[4 * j + 2] += dot * vv.z;
                acc[4 * j + 3] += dot * vv.w;
            }
        }
        __syncthreads();
    }

    float inv = 1.0f / (den + 1e-6f);
    float* orow = &g_attn[(size_t)(rowbase + row) * Edim + colbase];
#pragma unroll
    for (int j = 0; j < 16; j++) {
        float4 o;
        o.x = acc[4 * j + 0] * inv;
        o.y = acc[4 * j + 1] * inv;
        o.z = acc[4 * j + 2] * inv;
        o.w = acc[4 * j + 3] * inv;
        *(float4*)(orow + 4 * j) = o;
    }
}

// ---------------- LayerNorm --------------------------------------------------
__global__ void __launch_bounds__(256) v3_ln_kernel(
    const float* __restrict__ gamma, const float* __restrict__ beta,
    float* __restrict__ out)
{
    int row = blockIdx.x;
    int t = threadIdx.x;
    const float* yr = &g_y[(size_t)row * Edim];
    float4 v = *(const float4*)(yr + t * 4);
    float s = v.x + v.y + v.z + v.w;
    float ss = v.x * v.x + v.y * v.y + v.z * v.z + v.w * v.w;
#pragma unroll
    for (int o = 16; o; o >>= 1) {
        s += __shfl_down_sync(0xffffffffu, s, o);
        ss += __shfl_down_sync(0xffffffffu, ss, o);
    }
    __shared__ float sh_s[8], sh_ss[8];
    int w = t >> 5, ln = t & 31;
    if (ln == 0) { sh_s[w] = s; sh_ss[w] = ss; }
    __syncthreads();
    if (t == 0) {
        float a = 0.f, b2 = 0.f;
#pragma unroll
        for (int i = 0; i < 8; i++) { a += sh_s[i]; b2 += sh_ss[i]; }
        sh_s[0] = a; sh_ss[0] = b2;
    }
    __syncthreads();
    float mu = sh_s[0] * (1.0f / Edim);
    float var = sh_ss[0] * (1.0f / Edim) - mu * mu;
    float rstd = rsqrtf(var + 1e-5f);
    float4 g = *(const float4*)(gamma + t * 4);
    float4 bb = *(const float4*)(beta + t * 4);
    float4 o;
    o.x = g.x * (v.x - mu) * rstd + bb.x;
    o.y = g.y * (v.y - mu) * rstd + bb.y;
    o.z = g.z * (v.z - mu) * rstd + bb.z;
    o.w = g.w * (v.w - mu) * rstd + bb.w;
    *(float4*)(out + (size_t)row * Edim + t * 4) = o;
}

// ---------------- launch ------------------------------------------------------
extern "C" void kernel_launch(void* const* d_in, const int* in_sizes, int n_in,
                              void* d_out, int out_size)
{
    const float* x     = (const float*)d_in[0];
    const float* Wq    = (const float*)d_in[1];
    const float* bq    = (const float*)d_in[2];
    const float* Wk    = (const float*)d_in[3];
    const float* bk    = (const float*)d_in[4];
    const float* Wv    = (const float*)d_in[5];
    const float* bv    = (const float*)d_in[6];
    const float* Wo    = (const float*)d_in[7];
    const float* bo    = (const float*)d_in[8];
    const float* gamma = (const float*)d_in[9];
    const float* beta  = (const float*)d_in[10];
    float* out = (float*)d_out;

    cudaFuncSetAttribute(v3_gemm_kernel<1, 0, 0>, cudaFuncAttributeMaxDynamicSharedMemorySize, GSMB);
    cudaFuncSetAttribute(v3_gemm_kernel<1, 1, 0>, cudaFuncAttributeMaxDynamicSharedMemorySize, GSMB);
    cudaFuncSetAttribute(v3_gemm_kernel<0, 2, 0>, cudaFuncAttributeMaxDynamicSharedMemorySize, GSMB);
    cudaFuncSetAttribute(v3_gemm_kernel<2, 3, 1>, cudaFuncAttributeMaxDynamicSharedMemorySize, GSMB);

    dim3 ggrid(Edim / 128, BL / 128);

    v3_gemm_kernel<1, 0, 0><<<ggrid, 256, GSMB>>>(x, Wq, bq, nullptr);   // q = phi(x@Wq+bq)
    v3_gemm_kernel<1, 1, 0><<<ggrid, 256, GSMB>>>(x, Wk, bk, nullptr);   // k = phi(x@Wk+bk)
    v3_gemm_kernel<0, 2, 0><<<ggrid, 256, GSMB>>>(x, Wv, bv, nullptr);   // v = x@Wv+bv

    v3_chunk_stats_kernel<<<NCHUNKS, 512>>>();
    v3_scan_kernel<<<Bdim * Hn, 256>>>();
    v3_chunk_out_kernel<<<NCHUNKS * 2, 128>>>();

    v3_gemm_kernel<2, 3, 1><<<ggrid, 256, GSMB>>>(nullptr, Wo, bo, x);   // y = attn@Wo+bo+x

    v3_ln_kernel<<<BL, 256>>>(gamma, beta, out);
}